// round 11
// baseline (speedup 1.0000x reference)
#include <cuda_runtime.h>
#include <cuda_bf16.h>
#include <cuda_fp16.h>
#include <math.h>
#include <stdint.h>

#define T_DIM 512
#define B_DIM 64
#define N_DIM 1024
#define H_DIM 512
#define M_DIM (T_DIM*B_DIM)   // 32768 rows = (t,b)

// ================= scratch (device globals) =================
__device__ float g_bcat[N_DIM];
__device__ float g_xw[M_DIM*N_DIM];            // input projections [32768][1024]
__device__ float g_h[M_DIM*N_DIM];             // hidden history fp32
__device__ __half g_hfhi[M_DIM*N_DIM];         // hidden split hi (fp16)
__device__ __half g_hflo[M_DIM*N_DIM];         // hidden split lo (fp16)
__device__ __nv_bfloat16 g_Ahi[M_DIM*N_DIM];   // x split hi
__device__ __nv_bfloat16 g_Alo[M_DIM*N_DIM];   // x split lo
__device__ __nv_bfloat16 g_Whi[N_DIM*N_DIM];   // [Wih_f;Wih_b] split
__device__ __nv_bfloat16 g_Wlo[N_DIM*N_DIM];
__device__ __half g_W1f[N_DIM*N_DIM];          // W1[:,1024:2048] fp16 (single plane)
__device__ __nv_bfloat16 g_Whhhi[2*H_DIM*H_DIM]; // Whh split [dir][j][k]
__device__ __nv_bfloat16 g_Whhlo[2*H_DIM*H_DIM];
__device__ __nv_bfloat16 g_state_hi[2*2*B_DIM*H_DIM]; // ping-pong [buf][dir][b][k]
__device__ __nv_bfloat16 g_state_lo[2*2*B_DIM*H_DIM];
__device__ float g_sproj[B_DIM*N_DIM];         // s @ W1[:, :N]^T + b1
__device__ float g_spart[8*B_DIM*N_DIM];       // split-K partials for sproj
__device__ float g_epart[8*M_DIM];             // per-ntile partial logits
__device__ float g_attn[T_DIM*B_DIM];          // softmax weights

__device__ __forceinline__ void split_bf16(float a, __nv_bfloat16& hi, __nv_bfloat16& lo) {
    hi = __float2bfloat16(a);
    lo = __float2bfloat16(a - __bfloat162float(hi));
}
__device__ __forceinline__ void split_fp16(float a, __half& hi, __half& lo) {
    hi = __float2half(a);
    lo = __float2half(a - __half2float(hi));
}

// ---------------- mma.sync + cp.async + ldmatrix primitives ----------------
__device__ __forceinline__ void mma16816(float* d, const uint32_t* a, uint32_t b0, uint32_t b1) {
    asm volatile("mma.sync.aligned.m16n8k16.row.col.f32.bf16.bf16.f32 "
        "{%0,%1,%2,%3}, {%4,%5,%6,%7}, {%8,%9}, {%0,%1,%2,%3};"
        : "+f"(d[0]), "+f"(d[1]), "+f"(d[2]), "+f"(d[3])
        : "r"(a[0]), "r"(a[1]), "r"(a[2]), "r"(a[3]), "r"(b0), "r"(b1));
}
__device__ __forceinline__ void mma16816h(float* d, const uint32_t* a, uint32_t b0, uint32_t b1) {
    asm volatile("mma.sync.aligned.m16n8k16.row.col.f32.f16.f16.f32 "
        "{%0,%1,%2,%3}, {%4,%5,%6,%7}, {%8,%9}, {%0,%1,%2,%3};"
        : "+f"(d[0]), "+f"(d[1]), "+f"(d[2]), "+f"(d[3])
        : "r"(a[0]), "r"(a[1]), "r"(a[2]), "r"(a[3]), "r"(b0), "r"(b1));
}
__device__ __forceinline__ uint32_t smem_u32(const void* p) {
    uint32_t a;
    asm("{ .reg .u64 t; cvta.to.shared.u64 t, %1; cvt.u32.u64 %0, t; }" : "=r"(a) : "l"(p));
    return a;
}
#define LDSM_X4(r, addr) \
    asm volatile("ldmatrix.sync.aligned.m8n8.x4.shared.b16 {%0,%1,%2,%3}, [%4];" \
        : "=r"((r)[0]), "=r"((r)[1]), "=r"((r)[2]), "=r"((r)[3]) : "r"(addr))
#define CP_ASYNC16(dst_u32, src) \
    asm volatile("cp.async.cg.shared.global [%0], [%1], 16;" :: "r"(dst_u32), "l"(src))
#define CP_COMMIT() asm volatile("cp.async.commit_group;" ::: "memory")
#define CP_WAIT(n)  asm volatile("cp.async.wait_group %0;" :: "n"(n) : "memory")

// ---------------- prep: weights split + bias ----------------
__global__ void prep_w_kernel(const float* __restrict__ Wih_f, const float* __restrict__ Wih_b,
                              const float* __restrict__ bih_f, const float* __restrict__ bih_b,
                              const float* __restrict__ Whh_f, const float* __restrict__ Whh_b,
                              const float* __restrict__ W1)
{
    int idx = blockIdx.x * 256 + threadIdx.x;     // 0..1M-1
    int j = idx >> 10, k = idx & 1023;
    float wc = (j < 512) ? Wih_f[j*1024 + k] : Wih_b[(j-512)*1024 + k];
    __nv_bfloat16 hi, lo;
    split_bf16(wc, hi, lo);
    g_Whi[idx] = hi; g_Wlo[idx] = lo;
    g_W1f[idx] = __float2half(W1[j*2048 + 1024 + k]);
    if (idx < 2*H_DIM*H_DIM) {
        int d = idx >> 18;
        int off = idx & (H_DIM*H_DIM - 1);
        float wv = (d ? Whh_b : Whh_f)[off];
        split_bf16(wv, hi, lo);
        g_Whhhi[idx] = hi; g_Whhlo[idx] = lo;
    }
    if (idx < N_DIM) g_bcat[idx] = (idx < 512) ? bih_f[idx] : bih_b[idx-512];
}

// ---------------- prep: x split ----------------
__global__ void prep_a_kernel(const float* __restrict__ x)
{
    int i4 = blockIdx.x * 256 + threadIdx.x;
    float4 v = ((const float4*)x)[i4];
    __nv_bfloat16 h0,h1,h2,h3,l0,l1,l2,l3;
    split_bf16(v.x,h0,l0); split_bf16(v.y,h1,l1);
    split_bf16(v.z,h2,l2); split_bf16(v.w,h3,l3);
    int base = i4 * 4;
    *(__nv_bfloat162*)&g_Ahi[base]   = __halves2bfloat162(h0,h1);
    *(__nv_bfloat162*)&g_Ahi[base+2] = __halves2bfloat162(h2,h3);
    *(__nv_bfloat162*)&g_Alo[base]   = __halves2bfloat162(l0,l1);
    *(__nv_bfloat162*)&g_Alo[base+2] = __halves2bfloat162(l2,l3);
}

// ================= mma.sync GEMM =================
// MODE 0: bf16 3-product (Ahi,Alo,Bhi,Blo): C[r][n] = acc + bias[n]
// MODE 1: fp16 2-product (Ahi,Alo,B): v=tanh(acc+sproj); epart[bx][r]=sum v*w2
// Inner loops are product-OUTER: same-accumulator mma reuse distance = 16
// (vs 3 before) so HMMA latency (~24cyc) is hidden at issue rate.
#define SA 40
#define ARR_B (128*SA*2)
#define MM_STAGES 4
#define MM0_SMEM (MM_STAGES*4*ARR_B)   // 163840
#define MM1_SMEM (MM_STAGES*3*ARR_B)   // 122880
template<int MODE>
__global__ void __launch_bounds__(256) mm_kernel(
    const __nv_bfloat16* __restrict__ Ahi, const __nv_bfloat16* __restrict__ Alo,
    const __nv_bfloat16* __restrict__ Bhi, const __nv_bfloat16* __restrict__ Blo,
    const float* __restrict__ bias,
    const float* __restrict__ sproj, const float* __restrict__ w2,
    float* __restrict__ C)
{
    extern __shared__ char smem[];
    const uint32_t sb = smem_u32(smem);
    constexpr int NARR = (MODE == 0) ? 4 : 3;
    constexpr uint32_t STG = (uint32_t)(NARR * ARR_B);

    const int tid = threadIdx.x;
    const int wid = tid >> 5, lane = tid & 31;
    const int warp_m = wid & 3, warp_n = wid >> 2;
    const int g = lane >> 2, q = lane & 3;
    const int n0 = blockIdx.x * 128;
    const int m0 = blockIdx.y * 128;

    const int l = lane;
    const uint32_t aoffB = (uint32_t)((((l & 7) + ((l >> 3) & 1) * 8) * SA + ((l >> 4) * 8))) * 2u;
    const uint32_t boffB = (uint32_t)(((((l >> 4) * 8) + (l & 7)) * SA + (((l >> 3) & 1) * 8))) * 2u;

    const int row0c = tid >> 2, sc0 = tid & 3;
    const int row1c = (tid + 256) >> 2, sc1 = (tid + 256) & 3;

    auto issue_chunk = [&](int kc) {
        uint32_t sbase = sb + (uint32_t)(kc % MM_STAGES) * STG;
        int col0 = kc * 32 + sc0 * 8;
        int col1 = kc * 32 + sc1 * 8;
        uint32_t so0 = (uint32_t)(row0c * (SA*2) + sc0 * 16);
        uint32_t so1 = (uint32_t)(row1c * (SA*2) + sc1 * 16);
        CP_ASYNC16(sbase + 0*ARR_B + so0, Ahi + (size_t)(m0 + row0c)*1024 + col0);
        CP_ASYNC16(sbase + 0*ARR_B + so1, Ahi + (size_t)(m0 + row1c)*1024 + col1);
        CP_ASYNC16(sbase + 1*ARR_B + so0, Alo + (size_t)(m0 + row0c)*1024 + col0);
        CP_ASYNC16(sbase + 1*ARR_B + so1, Alo + (size_t)(m0 + row1c)*1024 + col1);
        CP_ASYNC16(sbase + 2*ARR_B + so0, Bhi + (size_t)(n0 + row0c)*1024 + col0);
        CP_ASYNC16(sbase + 2*ARR_B + so1, Bhi + (size_t)(n0 + row1c)*1024 + col1);
        if (MODE == 0) {
            CP_ASYNC16(sbase + 3*ARR_B + so0, Blo + (size_t)(n0 + row0c)*1024 + col0);
            CP_ASYNC16(sbase + 3*ARR_B + so1, Blo + (size_t)(n0 + row1c)*1024 + col1);
        }
        CP_COMMIT();
    };

    float acc[2][8][4];
    #pragma unroll
    for (int mt = 0; mt < 2; mt++)
        #pragma unroll
        for (int nt = 0; nt < 8; nt++)
            #pragma unroll
            for (int i = 0; i < 4; i++) acc[mt][nt][i] = 0.f;

    issue_chunk(0);
    issue_chunk(1);
    issue_chunk(2);

    const int NC = 32;
    for (int kc = 0; kc < NC; ++kc) {
        CP_WAIT(2);
        __syncthreads();
        if (kc + 3 < NC) issue_chunk(kc + 3);
        else CP_COMMIT();                    // keep group count constant (hard guarantee)

        const uint32_t stage = sb + (uint32_t)(kc % MM_STAGES) * STG;
        const uint32_t aHi = stage + (uint32_t)(warp_m*32*SA*2) + aoffB;
        const uint32_t aLo = aHi + ARR_B;
        const uint32_t bHi = stage + 2*ARR_B + (uint32_t)(warp_n*64*SA*2) + boffB;

        #pragma unroll
        for (int ks = 0; ks < 2; ks++) {
            const uint32_t ko = (uint32_t)(ks * 32);
            // --- load ALL fragments for this k-slice first ---
            uint32_t ah[2][4], al[2][4];
            #pragma unroll
            for (int mt = 0; mt < 2; mt++) {
                LDSM_X4(ah[mt], aHi + (uint32_t)(mt*16*SA*2) + ko);
                LDSM_X4(al[mt], aLo + (uint32_t)(mt*16*SA*2) + ko);
            }
            uint32_t bh[4][4];
            #pragma unroll
            for (int ntp = 0; ntp < 4; ntp++)
                LDSM_X4(bh[ntp], bHi + (uint32_t)(ntp*16*SA*2) + ko);

            if (MODE == 0) {
                uint32_t bl[4][4];
                #pragma unroll
                for (int ntp = 0; ntp < 4; ntp++)
                    LDSM_X4(bl[ntp], bHi + ARR_B + (uint32_t)(ntp*16*SA*2) + ko);
                // --- product-outer: 16 independent acc per product sweep ---
                #pragma unroll
                for (int ntp = 0; ntp < 4; ntp++)
                    #pragma unroll
                    for (int half = 0; half < 2; half++)
                        #pragma unroll
                        for (int mt = 0; mt < 2; mt++)
                            mma16816(acc[mt][ntp*2+half], ah[mt], bh[ntp][half*2], bh[ntp][half*2+1]);
                #pragma unroll
                for (int ntp = 0; ntp < 4; ntp++)
                    #pragma unroll
                    for (int half = 0; half < 2; half++)
                        #pragma unroll
                        for (int mt = 0; mt < 2; mt++)
                            mma16816(acc[mt][ntp*2+half], ah[mt], bl[ntp][half*2], bl[ntp][half*2+1]);
                #pragma unroll
                for (int ntp = 0; ntp < 4; ntp++)
                    #pragma unroll
                    for (int half = 0; half < 2; half++)
                        #pragma unroll
                        for (int mt = 0; mt < 2; mt++)
                            mma16816(acc[mt][ntp*2+half], al[mt], bh[ntp][half*2], bh[ntp][half*2+1]);
            } else {
                #pragma unroll
                for (int ntp = 0; ntp < 4; ntp++)
                    #pragma unroll
                    for (int half = 0; half < 2; half++)
                        #pragma unroll
                        for (int mt = 0; mt < 2; mt++)
                            mma16816h(acc[mt][ntp*2+half], ah[mt], bh[ntp][half*2], bh[ntp][half*2+1]);
                #pragma unroll
                for (int ntp = 0; ntp < 4; ntp++)
                    #pragma unroll
                    for (int half = 0; half < 2; half++)
                        #pragma unroll
                        for (int mt = 0; mt < 2; mt++)
                            mma16816h(acc[mt][ntp*2+half], al[mt], bh[ntp][half*2], bh[ntp][half*2+1]);
            }
        }
    }
    __syncthreads();

    if (MODE == 0) {
        #pragma unroll
        for (int mt = 0; mt < 2; mt++) {
            const int r = m0 + warp_m*32 + mt*16 + g;
            #pragma unroll
            for (int nt = 0; nt < 8; nt++) {
                const int c = n0 + warp_n*64 + nt*8 + q*2;
                float b0 = bias[c], b1 = bias[c+1];
                float2 v0 = make_float2(acc[mt][nt][0] + b0, acc[mt][nt][1] + b1);
                float2 v1 = make_float2(acc[mt][nt][2] + b0, acc[mt][nt][3] + b1);
                *(float2*)&C[(size_t)r*1024 + c]       = v0;
                *(float2*)&C[(size_t)(r+8)*1024 + c]   = v1;
            }
        }
    } else {
        float* red = (float*)smem;
        #pragma unroll
        for (int mt = 0; mt < 2; mt++) {
            const int rloc0 = warp_m*32 + mt*16 + g;
            const float* sp0 = &sproj[((m0 + rloc0)     & 63) * N_DIM];
            const float* sp1 = &sproj[((m0 + rloc0 + 8) & 63) * N_DIM];
            float s0 = 0.f, s1 = 0.f;
            #pragma unroll
            for (int nt = 0; nt < 8; nt++) {
                const int c = n0 + warp_n*64 + nt*8 + q*2;
                float w20 = w2[c], w21 = w2[c+1];
                s0 += tanhf(acc[mt][nt][0] + sp0[c])   * w20
                    + tanhf(acc[mt][nt][1] + sp0[c+1]) * w21;
                s1 += tanhf(acc[mt][nt][2] + sp1[c])   * w20
                    + tanhf(acc[mt][nt][3] + sp1[c+1]) * w21;
            }
            s0 += __shfl_xor_sync(0xffffffffu, s0, 1);
            s0 += __shfl_xor_sync(0xffffffffu, s0, 2);
            s1 += __shfl_xor_sync(0xffffffffu, s1, 1);
            s1 += __shfl_xor_sync(0xffffffffu, s1, 2);
            if (q == 0) {
                red[rloc0*2 + warp_n]     = s0;
                red[(rloc0+8)*2 + warp_n] = s1;
            }
        }
        __syncthreads();
        if (tid < 128)
            C[blockIdx.x * M_DIM + m0 + tid] = red[tid*2] + red[tid*2 + 1];
    }
}

// ---------------- sproj: split-K fp32 SIMT GEMM + reduce ----------------
__global__ void __launch_bounds__(256) gemm_small(
    const float* __restrict__ A, const float* __restrict__ Bw)
{
    __shared__ float As[16][128];
    __shared__ float Bs[16][128];

    const int tid  = threadIdx.x;
    const int n0   = blockIdx.x * 128;
    const int kb   = blockIdx.y * 128;
    const int lrow = tid >> 2;
    const int lcol = (tid & 3) << 2;
    const int rm   = (tid >> 4) << 3;
    const int rn   = (tid & 15) << 3;

    float4 pa0, pb0, pb1;
    auto loadg = [&](int kt) {
        float4 z; z.x = z.y = z.z = z.w = 0.f;
        pa0 = (lrow < 64) ? *(const float4*)&A[lrow*1024 + kb + kt + lcol] : z;
        pb0 = *(const float4*)&Bw[(n0 + lrow)      * 2048 + kb + kt + lcol];
        pb1 = *(const float4*)&Bw[(n0 + lrow + 64) * 2048 + kb + kt + lcol];
    };
    auto stores = [&]() {
        if (lrow < 64) {
            As[lcol+0][lrow] = pa0.x; As[lcol+1][lrow] = pa0.y;
            As[lcol+2][lrow] = pa0.z; As[lcol+3][lrow] = pa0.w;
        } else {
            int lr = lrow - 64;
            As[lcol+0][lr+64] = 0.f; As[lcol+1][lr+64] = 0.f;
            As[lcol+2][lr+64] = 0.f; As[lcol+3][lr+64] = 0.f;
        }
        Bs[lcol+0][lrow]    = pb0.x; Bs[lcol+1][lrow]    = pb0.y;
        Bs[lcol+2][lrow]    = pb0.z; Bs[lcol+3][lrow]    = pb0.w;
        Bs[lcol+0][lrow+64] = pb1.x; Bs[lcol+1][lrow+64] = pb1.y;
        Bs[lcol+2][lrow+64] = pb1.z; Bs[lcol+3][lrow+64] = pb1.w;
    };

    float acc[8][8];
    #pragma unroll
    for (int i = 0; i < 8; i++)
        #pragma unroll
        for (int j = 0; j < 8; j++) acc[i][j] = 0.f;

    loadg(0); stores(); __syncthreads();
    const int NIT = 8;
    for (int it = 0; it < NIT; ++it) {
        if (it + 1 < NIT) loadg((it + 1) * 16);
        #pragma unroll
        for (int k = 0; k < 16; k++) {
            float4 a0 = *(const float4*)&As[k][rm];
            float4 a1 = *(const float4*)&As[k][rm + 4];
            float4 b0 = *(const float4*)&Bs[k][rn];
            float4 b1 = *(const float4*)&Bs[k][rn + 4];
            float av[8] = {a0.x,a0.y,a0.z,a0.w,a1.x,a1.y,a1.z,a1.w};
            float bv[8] = {b0.x,b0.y,b0.z,b0.w,b1.x,b1.y,b1.z,b1.w};
            #pragma unroll
            for (int i = 0; i < 8; i++)
                #pragma unroll
                for (int j = 0; j < 8; j++)
                    acc[i][j] += av[i] * bv[j];
        }
        if (it + 1 < NIT) { __syncthreads(); stores(); __syncthreads(); }
    }
    float* Cp = &g_spart[blockIdx.y * (B_DIM*N_DIM)];
    #pragma unroll
    for (int i = 0; i < 8; i++) {
        int rr = rm + i;
        if (rr < 64) {
            #pragma unroll
            for (int j = 0; j < 8; j++)
                Cp[rr*1024 + n0 + rn + j] = acc[i][j];
        }
    }
}

__global__ void __launch_bounds__(256) reduce_sproj(const float* __restrict__ b1)
{
    int idx = blockIdx.x * 256 + threadIdx.x;
    float s = b1[idx & 1023];
    #pragma unroll
    for (int k = 0; k < 8; k++) s += g_spart[k * (B_DIM*N_DIM) + idx];
    g_sproj[idx] = s;
}

// ---------------- bidirectional recurrence: tensor-core, split cluster barrier ----------------
#define RSA 520
#define RNN_HS_B (16*RSA*2)
#define RED_S 68
#define RNN_RED_OFF (2*RNN_HS_B)
#define RNN_SMEM (RNN_RED_OFF + 8*16*RED_S*4)

__global__ void __launch_bounds__(256) __cluster_dims__(8, 1, 1)
rnn_kernel(const float* __restrict__ bhh_f, const float* __restrict__ bhh_b)
{
    extern __shared__ char smem[];
    float* red = (float*)(smem + RNN_RED_OFF);
    const uint32_t sb = smem_u32(smem);

    const int tid = threadIdx.x;
    const int wid = tid >> 5, lane = tid & 31;
    const int g = lane >> 2, q = lane & 3;
    const int bx = blockIdx.x;
    const int cid = bx >> 3;
    const int jtile = bx & 7;
    const int dir = cid >> 2;
    const int btile = cid & 3;

    const float* bhh = dir ? bhh_b : bhh_f;
    const __nv_bfloat16* Whi = g_Whhhi + dir * (H_DIM*H_DIM);
    const __nv_bfloat16* Wlo = g_Whhlo + dir * (H_DIM*H_DIM);

    uint32_t bh[8][4][2], bl[8][4][2];
    #pragma unroll
    for (int nt = 0; nt < 8; nt++) {
        int jg = jtile*64 + nt*8 + g;
        #pragma unroll
        for (int kt = 0; kt < 4; kt++) {
            int k = wid*64 + kt*16 + q*2;
            bh[nt][kt][0] = *(const uint32_t*)&Whi[jg*512 + k];
            bh[nt][kt][1] = *(const uint32_t*)&Whi[jg*512 + k + 8];
            bl[nt][kt][0] = *(const uint32_t*)&Wlo[jg*512 + k];
            bl[nt][kt][1] = *(const uint32_t*)&Wlo[jg*512 + k + 8];
        }
    }

    const int l = lane;
    const uint32_t aoffR = (uint32_t)((((l & 7) + ((l >> 3) & 1) * 8) * RSA + ((l >> 4) * 8))) * 2u;

    for (int o = tid; o < 16*64; o += 256) {
        int b = btile*16 + (o >> 6);
        int j = jtile*64 + (o & 63);
        int idx = (dir*64 + b)*512 + j;
        g_state_hi[idx] = __float2bfloat16(0.f);
        g_state_lo[idx] = __float2bfloat16(0.f);
    }
    asm volatile("barrier.cluster.arrive.release.aligned;\n\t"
                 "barrier.cluster.wait.acquire.aligned;" ::: "memory");

    const int fb  = tid >> 4;
    const int fj4 = (tid & 15) * 4;
    const int bg  = btile*16 + fb;
    const int jg0 = jtile*64 + fj4;
    const float4 bj = *(const float4*)&bhh[jg0];

    for (int t = 0; t < T_DIM; ++t) {
        const int rbuf = t & 1, wbuf = rbuf ^ 1;
        const int tt  = dir ? (T_DIM - 1 - t) : t;
        const size_t hidx = (size_t)(tt*64 + bg)*1024 + dir*512 + jg0;
        float4 xwv = *(const float4*)&g_xw[hidx];

        {
            const __nv_bfloat16* shi = g_state_hi + ((rbuf*2 + dir)*64 + btile*16)*512;
            const __nv_bfloat16* slo = g_state_lo + ((rbuf*2 + dir)*64 + btile*16)*512;
            #pragma unroll
            for (int i = 0; i < 8; i++) {
                int c = tid + i*256;
                int plane = c >> 10, rr = (c >> 6) & 15, seg = c & 63;
                const __nv_bfloat16* sp = (plane ? slo : shi) + rr*512 + seg*8;
                uint32_t dst = sb + (plane ? RNN_HS_B : 0) + (uint32_t)(rr*1040 + seg*16);
                CP_ASYNC16(dst, sp);
            }
            CP_COMMIT();
            CP_WAIT(0);
        }
        __syncthreads();

        float acc[8][4];
        #pragma unroll
        for (int nt = 0; nt < 8; nt++)
            #pragma unroll
            for (int i = 0; i < 4; i++) acc[nt][i] = 0.f;

        #pragma unroll
        for (int kt = 0; kt < 4; kt++) {
            const uint32_t kByte = (uint32_t)((wid*64 + kt*16) * 2);
            uint32_t ah[4], al[4];
            LDSM_X4(ah, sb + kByte + aoffR);
            LDSM_X4(al, sb + RNN_HS_B + kByte + aoffR);
            // product-outer: same-acc reuse distance 8
            #pragma unroll
            for (int nt = 0; nt < 8; nt++)
                mma16816(acc[nt], ah, bh[nt][kt][0], bh[nt][kt][1]);
            #pragma unroll
            for (int nt = 0; nt < 8; nt++)
                mma16816(acc[nt], ah, bl[nt][kt][0], bl[nt][kt][1]);
            #pragma unroll
            for (int nt = 0; nt < 8; nt++)
                mma16816(acc[nt], al, bh[nt][kt][0], bh[nt][kt][1]);
        }

        #pragma unroll
        for (int nt = 0; nt < 8; nt++) {
            *(float2*)&red[(wid*16 + g)*RED_S + nt*8 + q*2]     = make_float2(acc[nt][0], acc[nt][1]);
            *(float2*)&red[(wid*16 + g + 8)*RED_S + nt*8 + q*2] = make_float2(acc[nt][2], acc[nt][3]);
        }
        __syncthreads();

        {
            float4 s = make_float4(0.f, 0.f, 0.f, 0.f);
            #pragma unroll
            for (int w8 = 0; w8 < 8; w8++) {
                float4 p = *(const float4*)&red[(w8*16 + fb)*RED_S + fj4];
                s.x += p.x; s.y += p.y; s.z += p.z; s.w += p.w;
            }
            float v0 = tanhf(s.x + xwv.x + bj.x);
            float v1 = tanhf(s.y + xwv.y + bj.y);
            float v2 = tanhf(s.z + xwv.z + bj.z);
            float v3 = tanhf(s.w + xwv.w + bj.w);

            __nv_bfloat16 h0,h1,h2,h3,l0,l1,l2,l3;
            split_bf16(v0,h0,l0); split_bf16(v1,h1,l1);
            split_bf16(v2,h2,l2); split_bf16(v3,h3,l3);

            // peer-visible state stores; each thread's own arrive.release orders
            // its stores, and the barrier propagates to all waiters — no extra
            // __syncthreads needed before arrive.
            const size_t sidx = ((size_t)(wbuf*2 + dir)*64 + bg)*512 + jg0;
            *(__nv_bfloat162*)&g_state_hi[sidx]   = __halves2bfloat162(h0,h1);
            *(__nv_bfloat162*)&g_state_hi[sidx+2] = __halves2bfloat162(h2,h3);
            *(__nv_bfloat162*)&g_state_lo[sidx]   = __halves2bfloat162(l0,l1);
            *(__nv_bfloat162*)&g_state_lo[sidx+2] = __halves2bfloat162(l2,l3);
            asm volatile("barrier.cluster.arrive.release.aligned;" ::: "memory");

            // history stores overlap the barrier wait (fp16 planes for mm mode1)
            *(float4*)&g_h[hidx] = make_float4(v0,v1,v2,v3);
            __half f0,f1,f2,f3,e0,e1,e2,e3;
            split_fp16(v0,f0,e0); split_fp16(v1,f1,e1);
            split_fp16(v2,f2,e2); split_fp16(v3,f3,e3);
            *(__half2*)&g_hfhi[hidx]   = __halves2half2(f0,f1);
            *(__half2*)&g_hfhi[hidx+2] = __halves2half2(f2,f3);
            *(__half2*)&g_hflo[hidx]   = __halves2half2(e0,e1);
            *(__half2*)&g_hflo[hidx+2] = __halves2half2(e2,e3);

            asm volatile("barrier.cluster.wait.acquire.aligned;" ::: "memory");
        }
    }
}

// ---------------- softmax over time ----------------
__global__ void __launch_bounds__(512) softmax_kernel(const float* __restrict__ b2)
{
    const int b = blockIdx.x;
    const int t = threadIdx.x;
    float s = 0.f;
    #pragma unroll
    for (int p = 0; p < 8; p++) s += g_epart[p * M_DIM + t * 64 + b];
    float e = tanhf(s + b2[0]);

    __shared__ float sm[512];
    sm[t] = e; __syncthreads();
    for (int st = 256; st > 0; st >>= 1) {
        if (t < st) sm[t] = fmaxf(sm[t], sm[t + st]);
        __syncthreads();
    }
    float mx = sm[0]; __syncthreads();
    float ex = expf(e - mx);
    sm[t] = ex; __syncthreads();
    for (int st = 256; st > 0; st >>= 1) {
        if (t < st) sm[t] += sm[t + st];
        __syncthreads();
    }
    g_attn[t * 64 + b] = ex / sm[0];
}

// ---------------- weighted sum over time ----------------
__global__ void __launch_bounds__(256) out_kernel(float* __restrict__ out)
{
    const int b  = blockIdx.x;
    const int n  = blockIdx.y * 256 + threadIdx.x;
    __shared__ float a_s[512];
    for (int t = threadIdx.x; t < 512; t += 256) a_s[t] = g_attn[t * 64 + b];
    __syncthreads();
    float acc = 0.f;
    const float* hp = &g_h[(size_t)b * 1024 + n];
    #pragma unroll 8
    for (int t = 0; t < 512; t++) acc += a_s[t] * hp[(size_t)t * 65536];
    out[b * 1024 + n] = acc;
}

// ---------------- launch ----------------
extern "C" void kernel_launch(void* const* d_in, const int* in_sizes, int n_in,
                              void* d_out, int out_size)
{
    const float* s     = (const float*)d_in[0];
    const float* x     = (const float*)d_in[1];
    const float* Wih_f = (const float*)d_in[2];
    const float* Whh_f = (const float*)d_in[3];
    const float* bih_f = (const float*)d_in[4];
    const float* bhh_f = (const float*)d_in[5];
    const float* Wih_b = (const float*)d_in[6];
    const float* Whh_b = (const float*)d_in[7];
    const float* bih_b = (const float*)d_in[8];
    const float* bhh_b = (const float*)d_in[9];
    const float* W1    = (const float*)d_in[10];
    const float* b1    = (const float*)d_in[11];
    const float* W2    = (const float*)d_in[12];
    const float* b2    = (const float*)d_in[13];
    float* out = (float*)d_out;

    float *p_bcat, *p_xw, *p_sproj, *p_epart;
    __nv_bfloat16 *p_Ahi, *p_Alo, *p_Whi, *p_Wlo;
    __half *p_W1f, *p_hfhi, *p_hflo;
    cudaGetSymbolAddress((void**)&p_bcat,  g_bcat);
    cudaGetSymbolAddress((void**)&p_xw,    g_xw);
    cudaGetSymbolAddress((void**)&p_sproj, g_sproj);
    cudaGetSymbolAddress((void**)&p_epart, g_epart);
    cudaGetSymbolAddress((void**)&p_Ahi,   g_Ahi);
    cudaGetSymbolAddress((void**)&p_Alo,   g_Alo);
    cudaGetSymbolAddress((void**)&p_Whi,   g_Whi);
    cudaGetSymbolAddress((void**)&p_Wlo,   g_Wlo);
    cudaGetSymbolAddress((void**)&p_W1f,   g_W1f);
    cudaGetSymbolAddress((void**)&p_hfhi,  g_hfhi);
    cudaGetSymbolAddress((void**)&p_hflo,  g_hflo);

    cudaFuncSetAttribute(mm_kernel<0>, cudaFuncAttributeMaxDynamicSharedMemorySize, MM0_SMEM);
    cudaFuncSetAttribute(mm_kernel<1>, cudaFuncAttributeMaxDynamicSharedMemorySize, MM1_SMEM);
    cudaFuncSetAttribute(rnn_kernel,   cudaFuncAttributeMaxDynamicSharedMemorySize, RNN_SMEM);

    // 1. split weights + bias
    prep_w_kernel<<<4096, 256>>>(Wih_f, Wih_b, bih_f, bih_b, Whh_f, Whh_b, W1);
    // 2. split x
    prep_a_kernel<<<32768, 256>>>(x);
    // 3. xw = x @ Wcat^T + bcat   (bf16 3-product, product-outer)
    mm_kernel<0><<<dim3(8, 256), 256, MM0_SMEM>>>(p_Ahi, p_Alo, p_Whi, p_Wlo,
                                                  p_bcat, nullptr, nullptr, p_xw);
    // 4. sproj = s @ W1[:, :N]^T + b1 (split-K + reduce)
    gemm_small<<<dim3(8, 8), 256>>>(s, W1);
    reduce_sproj<<<256, 256>>>(b1);
    // 5. bidirectional recurrence (tensor cores, split cluster barrier)
    rnn_kernel<<<64, 256, RNN_SMEM>>>(bhh_f, bhh_b);
    // 6. attention MLP + dot with w2 (fp16 2-product, product-outer)
    mm_kernel<1><<<dim3(8, 256), 256, MM1_SMEM>>>(
        (const __nv_bfloat16*)p_hfhi, (const __nv_bfloat16*)p_hflo,
        (const __nv_bfloat16*)p_W1f, nullptr,
        nullptr, p_sproj, W2, p_epart);
    // 7. softmax over time
    softmax_kernel<<<64, 512>>>(b2);
    // 8. weighted sum -> output [B, N]
    out_kernel<<<dim3(64, 4), 256>>>(out);
}

// round 12
// speedup vs baseline: 1.0416x; 1.0416x over previous
#include <cuda_runtime.h>
#include <cuda_bf16.h>
#include <cuda_fp16.h>
#include <math.h>
#include <stdint.h>

#define T_DIM 512
#define B_DIM 64
#define N_DIM 1024
#define H_DIM 512
#define M_DIM (T_DIM*B_DIM)   // 32768 rows = (t,b)

// ================= scratch (device globals) =================
__device__ float g_bcat[N_DIM];
__device__ float g_xw[M_DIM*N_DIM];            // input projections [32768][1024]
__device__ float g_h[M_DIM*N_DIM];             // hidden history fp32
__device__ __half g_hfhi[M_DIM*N_DIM];         // hidden split hi (fp16)
__device__ __half g_hflo[M_DIM*N_DIM];         // hidden split lo (fp16)
__device__ __nv_bfloat16 g_Ahi[M_DIM*N_DIM];   // x split hi
__device__ __nv_bfloat16 g_Alo[M_DIM*N_DIM];   // x split lo
__device__ __nv_bfloat16 g_Whi[N_DIM*N_DIM];   // [Wih_f;Wih_b] split
__device__ __nv_bfloat16 g_Wlo[N_DIM*N_DIM];
__device__ __half g_W1f[N_DIM*N_DIM];          // W1[:,1024:2048] fp16 (single plane)
__device__ __nv_bfloat16 g_Whhhi[2*H_DIM*H_DIM]; // Whh split [dir][j][k]
__device__ __nv_bfloat16 g_Whhlo[2*H_DIM*H_DIM];
__device__ __nv_bfloat16 g_state_hi[2*2*B_DIM*H_DIM]; // ping-pong [buf][dir][b][k]
__device__ __nv_bfloat16 g_state_lo[2*2*B_DIM*H_DIM];
__device__ float g_sproj[B_DIM*N_DIM];         // s @ W1[:, :N]^T + b1
__device__ float g_spart[8*B_DIM*N_DIM];       // split-K partials for sproj
__device__ float g_epart[8*M_DIM];             // per-ntile partial logits
__device__ float g_attn[T_DIM*B_DIM];          // softmax weights

__device__ __forceinline__ void split_bf16(float a, __nv_bfloat16& hi, __nv_bfloat16& lo) {
    hi = __float2bfloat16(a);
    lo = __float2bfloat16(a - __bfloat162float(hi));
}
__device__ __forceinline__ void split_fp16(float a, __half& hi, __half& lo) {
    hi = __float2half(a);
    lo = __float2half(a - __half2float(hi));
}

// ---------------- mma.sync + cp.async + ldmatrix primitives ----------------
__device__ __forceinline__ void mma16816(float* d, const uint32_t* a, uint32_t b0, uint32_t b1) {
    asm volatile("mma.sync.aligned.m16n8k16.row.col.f32.bf16.bf16.f32 "
        "{%0,%1,%2,%3}, {%4,%5,%6,%7}, {%8,%9}, {%0,%1,%2,%3};"
        : "+f"(d[0]), "+f"(d[1]), "+f"(d[2]), "+f"(d[3])
        : "r"(a[0]), "r"(a[1]), "r"(a[2]), "r"(a[3]), "r"(b0), "r"(b1));
}
__device__ __forceinline__ void mma16816h(float* d, const uint32_t* a, uint32_t b0, uint32_t b1) {
    asm volatile("mma.sync.aligned.m16n8k16.row.col.f32.f16.f16.f32 "
        "{%0,%1,%2,%3}, {%4,%5,%6,%7}, {%8,%9}, {%0,%1,%2,%3};"
        : "+f"(d[0]), "+f"(d[1]), "+f"(d[2]), "+f"(d[3])
        : "r"(a[0]), "r"(a[1]), "r"(a[2]), "r"(a[3]), "r"(b0), "r"(b1));
}
__device__ __forceinline__ uint32_t smem_u32(const void* p) {
    uint32_t a;
    asm("{ .reg .u64 t; cvta.to.shared.u64 t, %1; cvt.u32.u64 %0, t; }" : "=r"(a) : "l"(p));
    return a;
}
#define LDSM_X4(r, addr) \
    asm volatile("ldmatrix.sync.aligned.m8n8.x4.shared.b16 {%0,%1,%2,%3}, [%4];" \
        : "=r"((r)[0]), "=r"((r)[1]), "=r"((r)[2]), "=r"((r)[3]) : "r"(addr))
#define CP_ASYNC16(dst_u32, src) \
    asm volatile("cp.async.cg.shared.global [%0], [%1], 16;" :: "r"(dst_u32), "l"(src))
#define CP_COMMIT() asm volatile("cp.async.commit_group;" ::: "memory")
#define CP_WAIT(n)  asm volatile("cp.async.wait_group %0;" :: "n"(n) : "memory")

// ---------------- prep: weights split + bias ----------------
__global__ void prep_w_kernel(const float* __restrict__ Wih_f, const float* __restrict__ Wih_b,
                              const float* __restrict__ bih_f, const float* __restrict__ bih_b,
                              const float* __restrict__ Whh_f, const float* __restrict__ Whh_b,
                              const float* __restrict__ W1)
{
    int idx = blockIdx.x * 256 + threadIdx.x;     // 0..1M-1
    int j = idx >> 10, k = idx & 1023;
    float wc = (j < 512) ? Wih_f[j*1024 + k] : Wih_b[(j-512)*1024 + k];
    __nv_bfloat16 hi, lo;
    split_bf16(wc, hi, lo);
    g_Whi[idx] = hi; g_Wlo[idx] = lo;
    g_W1f[idx] = __float2half(W1[j*2048 + 1024 + k]);
    if (idx < 2*H_DIM*H_DIM) {
        int d = idx >> 18;
        int off = idx & (H_DIM*H_DIM - 1);
        float wv = (d ? Whh_b : Whh_f)[off];
        split_bf16(wv, hi, lo);
        g_Whhhi[idx] = hi; g_Whhlo[idx] = lo;
    }
    if (idx < N_DIM) g_bcat[idx] = (idx < 512) ? bih_f[idx] : bih_b[idx-512];
}

// ---------------- prep: x split ----------------
__global__ void prep_a_kernel(const float* __restrict__ x)
{
    int i4 = blockIdx.x * 256 + threadIdx.x;
    float4 v = ((const float4*)x)[i4];
    __nv_bfloat16 h0,h1,h2,h3,l0,l1,l2,l3;
    split_bf16(v.x,h0,l0); split_bf16(v.y,h1,l1);
    split_bf16(v.z,h2,l2); split_bf16(v.w,h3,l3);
    int base = i4 * 4;
    *(__nv_bfloat162*)&g_Ahi[base]   = __halves2bfloat162(h0,h1);
    *(__nv_bfloat162*)&g_Ahi[base+2] = __halves2bfloat162(h2,h3);
    *(__nv_bfloat162*)&g_Alo[base]   = __halves2bfloat162(l0,l1);
    *(__nv_bfloat162*)&g_Alo[base+2] = __halves2bfloat162(l2,l3);
}

// ================= mma.sync GEMM =================
// MODE 0: bf16 3-product (Ahi,Alo,Bhi,Blo): C[r][n] = acc + bias[n]
// MODE 1: fp16 2-product (Ahi,Alo,B): v=tanh(acc+sproj); epart[bx][r]=sum v*w2
#define SA 40
#define ARR_B (128*SA*2)
#define MM_STAGES 4
#define MM0_SMEM (MM_STAGES*4*ARR_B)   // 163840
#define MM1_SMEM (MM_STAGES*3*ARR_B)   // 122880
template<int MODE>
__global__ void __launch_bounds__(256) mm_kernel(
    const __nv_bfloat16* __restrict__ Ahi, const __nv_bfloat16* __restrict__ Alo,
    const __nv_bfloat16* __restrict__ Bhi, const __nv_bfloat16* __restrict__ Blo,
    const float* __restrict__ bias,
    const float* __restrict__ sproj, const float* __restrict__ w2,
    float* __restrict__ C)
{
    extern __shared__ char smem[];
    const uint32_t sb = smem_u32(smem);
    constexpr int NARR = (MODE == 0) ? 4 : 3;
    constexpr uint32_t STG = (uint32_t)(NARR * ARR_B);

    const int tid = threadIdx.x;
    const int wid = tid >> 5, lane = tid & 31;
    const int warp_m = wid & 3, warp_n = wid >> 2;
    const int g = lane >> 2, q = lane & 3;
    const int n0 = blockIdx.x * 128;
    const int m0 = blockIdx.y * 128;

    const int l = lane;
    const uint32_t aoffB = (uint32_t)((((l & 7) + ((l >> 3) & 1) * 8) * SA + ((l >> 4) * 8))) * 2u;
    const uint32_t boffB = (uint32_t)(((((l >> 4) * 8) + (l & 7)) * SA + (((l >> 3) & 1) * 8))) * 2u;

    const int row0c = tid >> 2, sc0 = tid & 3;
    const int row1c = (tid + 256) >> 2, sc1 = (tid + 256) & 3;

    auto issue_chunk = [&](int kc) {
        uint32_t sbase = sb + (uint32_t)(kc % MM_STAGES) * STG;
        int col0 = kc * 32 + sc0 * 8;
        int col1 = kc * 32 + sc1 * 8;
        uint32_t so0 = (uint32_t)(row0c * (SA*2) + sc0 * 16);
        uint32_t so1 = (uint32_t)(row1c * (SA*2) + sc1 * 16);
        CP_ASYNC16(sbase + 0*ARR_B + so0, Ahi + (size_t)(m0 + row0c)*1024 + col0);
        CP_ASYNC16(sbase + 0*ARR_B + so1, Ahi + (size_t)(m0 + row1c)*1024 + col1);
        CP_ASYNC16(sbase + 1*ARR_B + so0, Alo + (size_t)(m0 + row0c)*1024 + col0);
        CP_ASYNC16(sbase + 1*ARR_B + so1, Alo + (size_t)(m0 + row1c)*1024 + col1);
        CP_ASYNC16(sbase + 2*ARR_B + so0, Bhi + (size_t)(n0 + row0c)*1024 + col0);
        CP_ASYNC16(sbase + 2*ARR_B + so1, Bhi + (size_t)(n0 + row1c)*1024 + col1);
        if (MODE == 0) {
            CP_ASYNC16(sbase + 3*ARR_B + so0, Blo + (size_t)(n0 + row0c)*1024 + col0);
            CP_ASYNC16(sbase + 3*ARR_B + so1, Blo + (size_t)(n0 + row1c)*1024 + col1);
        }
        CP_COMMIT();
    };

    float acc[2][8][4];
    #pragma unroll
    for (int mt = 0; mt < 2; mt++)
        #pragma unroll
        for (int nt = 0; nt < 8; nt++)
            #pragma unroll
            for (int i = 0; i < 4; i++) acc[mt][nt][i] = 0.f;

    issue_chunk(0);
    issue_chunk(1);
    issue_chunk(2);

    const int NC = 32;
    for (int kc = 0; kc < NC; ++kc) {
        CP_WAIT(2);
        __syncthreads();
        if (kc + 3 < NC) issue_chunk(kc + 3);
        else CP_COMMIT();                    // keep group count constant (hard guarantee)

        const uint32_t stage = sb + (uint32_t)(kc % MM_STAGES) * STG;
        const uint32_t aHi = stage + (uint32_t)(warp_m*32*SA*2) + aoffB;
        const uint32_t aLo = aHi + ARR_B;
        const uint32_t bHi = stage + 2*ARR_B + (uint32_t)(warp_n*64*SA*2) + boffB;

        #pragma unroll
        for (int ks = 0; ks < 2; ks++) {
            const uint32_t ko = (uint32_t)(ks * 32);
            uint32_t ah[2][4], al[2][4];
            #pragma unroll
            for (int mt = 0; mt < 2; mt++) {
                LDSM_X4(ah[mt], aHi + (uint32_t)(mt*16*SA*2) + ko);
                LDSM_X4(al[mt], aLo + (uint32_t)(mt*16*SA*2) + ko);
            }
            #pragma unroll
            for (int ntp = 0; ntp < 4; ntp++) {
                uint32_t bh[4];
                LDSM_X4(bh, bHi + (uint32_t)(ntp*16*SA*2) + ko);
                if (MODE == 0) {
                    uint32_t bl[4];
                    LDSM_X4(bl, bHi + ARR_B + (uint32_t)(ntp*16*SA*2) + ko);
                    #pragma unroll
                    for (int half = 0; half < 2; half++) {
                        const int nt = ntp*2 + half;
                        #pragma unroll
                        for (int mt = 0; mt < 2; mt++) {
                            mma16816(acc[mt][nt], ah[mt], bh[half*2], bh[half*2+1]);
                            mma16816(acc[mt][nt], ah[mt], bl[half*2], bl[half*2+1]);
                            mma16816(acc[mt][nt], al[mt], bh[half*2], bh[half*2+1]);
                        }
                    }
                } else {
                    #pragma unroll
                    for (int half = 0; half < 2; half++) {
                        const int nt = ntp*2 + half;
                        #pragma unroll
                        for (int mt = 0; mt < 2; mt++) {
                            mma16816h(acc[mt][nt], ah[mt], bh[half*2], bh[half*2+1]);
                            mma16816h(acc[mt][nt], al[mt], bh[half*2], bh[half*2+1]);
                        }
                    }
                }
            }
        }
    }
    __syncthreads();

    if (MODE == 0) {
        #pragma unroll
        for (int mt = 0; mt < 2; mt++) {
            const int r = m0 + warp_m*32 + mt*16 + g;
            #pragma unroll
            for (int nt = 0; nt < 8; nt++) {
                const int c = n0 + warp_n*64 + nt*8 + q*2;
                float b0 = bias[c], b1 = bias[c+1];
                float2 v0 = make_float2(acc[mt][nt][0] + b0, acc[mt][nt][1] + b1);
                float2 v1 = make_float2(acc[mt][nt][2] + b0, acc[mt][nt][3] + b1);
                *(float2*)&C[(size_t)r*1024 + c]       = v0;
                *(float2*)&C[(size_t)(r+8)*1024 + c]   = v1;
            }
        }
    } else {
        float* red = (float*)smem;
        #pragma unroll
        for (int mt = 0; mt < 2; mt++) {
            const int rloc0 = warp_m*32 + mt*16 + g;
            const float* sp0 = &sproj[((m0 + rloc0)     & 63) * N_DIM];
            const float* sp1 = &sproj[((m0 + rloc0 + 8) & 63) * N_DIM];
            float s0 = 0.f, s1 = 0.f;
            #pragma unroll
            for (int nt = 0; nt < 8; nt++) {
                const int c = n0 + warp_n*64 + nt*8 + q*2;
                float w20 = w2[c], w21 = w2[c+1];
                s0 += tanhf(acc[mt][nt][0] + sp0[c])   * w20
                    + tanhf(acc[mt][nt][1] + sp0[c+1]) * w21;
                s1 += tanhf(acc[mt][nt][2] + sp1[c])   * w20
                    + tanhf(acc[mt][nt][3] + sp1[c+1]) * w21;
            }
            s0 += __shfl_xor_sync(0xffffffffu, s0, 1);
            s0 += __shfl_xor_sync(0xffffffffu, s0, 2);
            s1 += __shfl_xor_sync(0xffffffffu, s1, 1);
            s1 += __shfl_xor_sync(0xffffffffu, s1, 2);
            if (q == 0) {
                red[rloc0*2 + warp_n]     = s0;
                red[(rloc0+8)*2 + warp_n] = s1;
            }
        }
        __syncthreads();
        if (tid < 128)
            C[blockIdx.x * M_DIM + m0 + tid] = red[tid*2] + red[tid*2 + 1];
    }
}

// ---------------- sproj: split-K fp32 SIMT GEMM + reduce ----------------
__global__ void __launch_bounds__(256) gemm_small(
    const float* __restrict__ A, const float* __restrict__ Bw)
{
    __shared__ float As[16][128];
    __shared__ float Bs[16][128];

    const int tid  = threadIdx.x;
    const int n0   = blockIdx.x * 128;
    const int kb   = blockIdx.y * 128;
    const int lrow = tid >> 2;
    const int lcol = (tid & 3) << 2;
    const int rm   = (tid >> 4) << 3;
    const int rn   = (tid & 15) << 3;

    float4 pa0, pb0, pb1;
    auto loadg = [&](int kt) {
        float4 z; z.x = z.y = z.z = z.w = 0.f;
        pa0 = (lrow < 64) ? *(const float4*)&A[lrow*1024 + kb + kt + lcol] : z;
        pb0 = *(const float4*)&Bw[(n0 + lrow)      * 2048 + kb + kt + lcol];
        pb1 = *(const float4*)&Bw[(n0 + lrow + 64) * 2048 + kb + kt + lcol];
    };
    auto stores = [&]() {
        if (lrow < 64) {
            As[lcol+0][lrow] = pa0.x; As[lcol+1][lrow] = pa0.y;
            As[lcol+2][lrow] = pa0.z; As[lcol+3][lrow] = pa0.w;
        } else {
            int lr = lrow - 64;
            As[lcol+0][lr+64] = 0.f; As[lcol+1][lr+64] = 0.f;
            As[lcol+2][lr+64] = 0.f; As[lcol+3][lr+64] = 0.f;
        }
        Bs[lcol+0][lrow]    = pb0.x; Bs[lcol+1][lrow]    = pb0.y;
        Bs[lcol+2][lrow]    = pb0.z; Bs[lcol+3][lrow]    = pb0.w;
        Bs[lcol+0][lrow+64] = pb1.x; Bs[lcol+1][lrow+64] = pb1.y;
        Bs[lcol+2][lrow+64] = pb1.z; Bs[lcol+3][lrow+64] = pb1.w;
    };

    float acc[8][8];
    #pragma unroll
    for (int i = 0; i < 8; i++)
        #pragma unroll
        for (int j = 0; j < 8; j++) acc[i][j] = 0.f;

    loadg(0); stores(); __syncthreads();
    const int NIT = 8;
    for (int it = 0; it < NIT; ++it) {
        if (it + 1 < NIT) loadg((it + 1) * 16);
        #pragma unroll
        for (int k = 0; k < 16; k++) {
            float4 a0 = *(const float4*)&As[k][rm];
            float4 a1 = *(const float4*)&As[k][rm + 4];
            float4 b0 = *(const float4*)&Bs[k][rn];
            float4 b1 = *(const float4*)&Bs[k][rn + 4];
            float av[8] = {a0.x,a0.y,a0.z,a0.w,a1.x,a1.y,a1.z,a1.w};
            float bv[8] = {b0.x,b0.y,b0.z,b0.w,b1.x,b1.y,b1.z,b1.w};
            #pragma unroll
            for (int i = 0; i < 8; i++)
                #pragma unroll
                for (int j = 0; j < 8; j++)
                    acc[i][j] += av[i] * bv[j];
        }
        if (it + 1 < NIT) { __syncthreads(); stores(); __syncthreads(); }
    }
    float* Cp = &g_spart[blockIdx.y * (B_DIM*N_DIM)];
    #pragma unroll
    for (int i = 0; i < 8; i++) {
        int rr = rm + i;
        if (rr < 64) {
            #pragma unroll
            for (int j = 0; j < 8; j++)
                Cp[rr*1024 + n0 + rn + j] = acc[i][j];
        }
    }
}

__global__ void __launch_bounds__(256) reduce_sproj(const float* __restrict__ b1)
{
    int idx = blockIdx.x * 256 + threadIdx.x;
    float s = b1[idx & 1023];
    #pragma unroll
    for (int k = 0; k < 8; k++) s += g_spart[k * (B_DIM*N_DIM) + idx];
    g_sproj[idx] = s;
}

// ---------------- bidirectional recurrence: tensor-core, split cluster barrier ----------------
#define RSA 520
#define RNN_HS_B (16*RSA*2)
#define RED_S 68
#define RNN_RED_OFF (2*RNN_HS_B)
#define RNN_SMEM (RNN_RED_OFF + 8*16*RED_S*4)

__global__ void __launch_bounds__(256) __cluster_dims__(8, 1, 1)
rnn_kernel(const float* __restrict__ bhh_f, const float* __restrict__ bhh_b)
{
    extern __shared__ char smem[];
    float* red = (float*)(smem + RNN_RED_OFF);
    const uint32_t sb = smem_u32(smem);

    const int tid = threadIdx.x;
    const int wid = tid >> 5, lane = tid & 31;
    const int g = lane >> 2, q = lane & 3;
    const int bx = blockIdx.x;
    const int cid = bx >> 3;
    const int jtile = bx & 7;
    const int dir = cid >> 2;
    const int btile = cid & 3;

    const float* bhh = dir ? bhh_b : bhh_f;
    const __nv_bfloat16* Whi = g_Whhhi + dir * (H_DIM*H_DIM);
    const __nv_bfloat16* Wlo = g_Whhlo + dir * (H_DIM*H_DIM);

    uint32_t bh[8][4][2], bl[8][4][2];
    #pragma unroll
    for (int nt = 0; nt < 8; nt++) {
        int jg = jtile*64 + nt*8 + g;
        #pragma unroll
        for (int kt = 0; kt < 4; kt++) {
            int k = wid*64 + kt*16 + q*2;
            bh[nt][kt][0] = *(const uint32_t*)&Whi[jg*512 + k];
            bh[nt][kt][1] = *(const uint32_t*)&Whi[jg*512 + k + 8];
            bl[nt][kt][0] = *(const uint32_t*)&Wlo[jg*512 + k];
            bl[nt][kt][1] = *(const uint32_t*)&Wlo[jg*512 + k + 8];
        }
    }

    const int l = lane;
    const uint32_t aoffR = (uint32_t)((((l & 7) + ((l >> 3) & 1) * 8) * RSA + ((l >> 4) * 8))) * 2u;

    for (int o = tid; o < 16*64; o += 256) {
        int b = btile*16 + (o >> 6);
        int j = jtile*64 + (o & 63);
        int idx = (dir*64 + b)*512 + j;
        g_state_hi[idx] = __float2bfloat16(0.f);
        g_state_lo[idx] = __float2bfloat16(0.f);
    }
    asm volatile("barrier.cluster.arrive.release.aligned;\n\t"
                 "barrier.cluster.wait.acquire.aligned;" ::: "memory");

    const int fb  = tid >> 4;
    const int fj4 = (tid & 15) * 4;
    const int bg  = btile*16 + fb;
    const int jg0 = jtile*64 + fj4;
    const float4 bj = *(const float4*)&bhh[jg0];

    for (int t = 0; t < T_DIM; ++t) {
        const int rbuf = t & 1, wbuf = rbuf ^ 1;
        const int tt  = dir ? (T_DIM - 1 - t) : t;
        const size_t hidx = (size_t)(tt*64 + bg)*1024 + dir*512 + jg0;
        float4 xwv = *(const float4*)&g_xw[hidx];

        {
            const __nv_bfloat16* shi = g_state_hi + ((rbuf*2 + dir)*64 + btile*16)*512;
            const __nv_bfloat16* slo = g_state_lo + ((rbuf*2 + dir)*64 + btile*16)*512;
            #pragma unroll
            for (int i = 0; i < 8; i++) {
                int c = tid + i*256;
                int plane = c >> 10, rr = (c >> 6) & 15, seg = c & 63;
                const __nv_bfloat16* sp = (plane ? slo : shi) + rr*512 + seg*8;
                uint32_t dst = sb + (plane ? RNN_HS_B : 0) + (uint32_t)(rr*1040 + seg*16);
                CP_ASYNC16(dst, sp);
            }
            CP_COMMIT();
            CP_WAIT(0);
        }
        __syncthreads();

        float acc[8][4];
        #pragma unroll
        for (int nt = 0; nt < 8; nt++)
            #pragma unroll
            for (int i = 0; i < 4; i++) acc[nt][i] = 0.f;

        #pragma unroll
        for (int kt = 0; kt < 4; kt++) {
            const uint32_t kByte = (uint32_t)((wid*64 + kt*16) * 2);
            uint32_t ah[4], al[4];
            LDSM_X4(ah, sb + kByte + aoffR);
            LDSM_X4(al, sb + RNN_HS_B + kByte + aoffR);
            #pragma unroll
            for (int nt = 0; nt < 8; nt++) {
                mma16816(acc[nt], ah, bh[nt][kt][0], bh[nt][kt][1]);
                mma16816(acc[nt], ah, bl[nt][kt][0], bl[nt][kt][1]);
                mma16816(acc[nt], al, bh[nt][kt][0], bh[nt][kt][1]);
            }
        }

        #pragma unroll
        for (int nt = 0; nt < 8; nt++) {
            *(float2*)&red[(wid*16 + g)*RED_S + nt*8 + q*2]     = make_float2(acc[nt][0], acc[nt][1]);
            *(float2*)&red[(wid*16 + g + 8)*RED_S + nt*8 + q*2] = make_float2(acc[nt][2], acc[nt][3]);
        }
        __syncthreads();

        {
            float4 s = make_float4(0.f, 0.f, 0.f, 0.f);
            #pragma unroll
            for (int w8 = 0; w8 < 8; w8++) {
                float4 p = *(const float4*)&red[(w8*16 + fb)*RED_S + fj4];
                s.x += p.x; s.y += p.y; s.z += p.z; s.w += p.w;
            }
            float v0 = tanhf(s.x + xwv.x + bj.x);
            float v1 = tanhf(s.y + xwv.y + bj.y);
            float v2 = tanhf(s.z + xwv.z + bj.z);
            float v3 = tanhf(s.w + xwv.w + bj.w);

            __nv_bfloat16 h0,h1,h2,h3,l0,l1,l2,l3;
            split_bf16(v0,h0,l0); split_bf16(v1,h1,l1);
            split_bf16(v2,h2,l2); split_bf16(v3,h3,l3);

            const size_t sidx = ((size_t)(wbuf*2 + dir)*64 + bg)*512 + jg0;
            *(__nv_bfloat162*)&g_state_hi[sidx]   = __halves2bfloat162(h0,h1);
            *(__nv_bfloat162*)&g_state_hi[sidx+2] = __halves2bfloat162(h2,h3);
            *(__nv_bfloat162*)&g_state_lo[sidx]   = __halves2bfloat162(l0,l1);
            *(__nv_bfloat162*)&g_state_lo[sidx+2] = __halves2bfloat162(l2,l3);
            __syncthreads();   // all CTA threads' state stores done before arrive
            asm volatile("barrier.cluster.arrive.release.aligned;" ::: "memory");

            // history stores overlap the barrier wait (fp16 planes for mm mode1)
            *(float4*)&g_h[hidx] = make_float4(v0,v1,v2,v3);
            __half f0,f1,f2,f3,e0,e1,e2,e3;
            split_fp16(v0,f0,e0); split_fp16(v1,f1,e1);
            split_fp16(v2,f2,e2); split_fp16(v3,f3,e3);
            *(__half2*)&g_hfhi[hidx]   = __halves2half2(f0,f1);
            *(__half2*)&g_hfhi[hidx+2] = __halves2half2(f2,f3);
            *(__half2*)&g_hflo[hidx]   = __halves2half2(e0,e1);
            *(__half2*)&g_hflo[hidx+2] = __halves2half2(e2,e3);

            asm volatile("barrier.cluster.wait.acquire.aligned;" ::: "memory");
        }
    }
}

// ---------------- softmax over time ----------------
__global__ void __launch_bounds__(512) softmax_kernel(const float* __restrict__ b2)
{
    const int b = blockIdx.x;
    const int t = threadIdx.x;
    float s = 0.f;
    #pragma unroll
    for (int p = 0; p < 8; p++) s += g_epart[p * M_DIM + t * 64 + b];
    float e = tanhf(s + b2[0]);

    __shared__ float sm[512];
    sm[t] = e; __syncthreads();
    for (int st = 256; st > 0; st >>= 1) {
        if (t < st) sm[t] = fmaxf(sm[t], sm[t + st]);
        __syncthreads();
    }
    float mx = sm[0]; __syncthreads();
    float ex = expf(e - mx);
    sm[t] = ex; __syncthreads();
    for (int st = 256; st > 0; st >>= 1) {
        if (t < st) sm[t] += sm[t + st];
        __syncthreads();
    }
    g_attn[t * 64 + b] = ex / sm[0];
}

// ---------------- weighted sum over time ----------------
__global__ void __launch_bounds__(256) out_kernel(float* __restrict__ out)
{
    const int b  = blockIdx.x;
    const int n  = blockIdx.y * 256 + threadIdx.x;
    __shared__ float a_s[512];
    for (int t = threadIdx.x; t < 512; t += 256) a_s[t] = g_attn[t * 64 + b];
    __syncthreads();
    float acc = 0.f;
    const float* hp = &g_h[(size_t)b * 1024 + n];
    #pragma unroll 8
    for (int t = 0; t < 512; t++) acc += a_s[t] * hp[(size_t)t * 65536];
    out[b * 1024 + n] = acc;
}

// ---------------- launch ----------------
extern "C" void kernel_launch(void* const* d_in, const int* in_sizes, int n_in,
                              void* d_out, int out_size)
{
    const float* s     = (const float*)d_in[0];
    const float* x     = (const float*)d_in[1];
    const float* Wih_f = (const float*)d_in[2];
    const float* Whh_f = (const float*)d_in[3];
    const float* bih_f = (const float*)d_in[4];
    const float* bhh_f = (const float*)d_in[5];
    const float* Wih_b = (const float*)d_in[6];
    const float* Whh_b = (const float*)d_in[7];
    const float* bih_b = (const float*)d_in[8];
    const float* bhh_b = (const float*)d_in[9];
    const float* W1    = (const float*)d_in[10];
    const float* b1    = (const float*)d_in[11];
    const float* W2    = (const float*)d_in[12];
    const float* b2    = (const float*)d_in[13];
    float* out = (float*)d_out;

    float *p_bcat, *p_xw, *p_sproj, *p_epart;
    __nv_bfloat16 *p_Ahi, *p_Alo, *p_Whi, *p_Wlo;
    __half *p_W1f, *p_hfhi, *p_hflo;
    cudaGetSymbolAddress((void**)&p_bcat,  g_bcat);
    cudaGetSymbolAddress((void**)&p_xw,    g_xw);
    cudaGetSymbolAddress((void**)&p_sproj, g_sproj);
    cudaGetSymbolAddress((void**)&p_epart, g_epart);
    cudaGetSymbolAddress((void**)&p_Ahi,   g_Ahi);
    cudaGetSymbolAddress((void**)&p_Alo,   g_Alo);
    cudaGetSymbolAddress((void**)&p_Whi,   g_Whi);
    cudaGetSymbolAddress((void**)&p_Wlo,   g_Wlo);
    cudaGetSymbolAddress((void**)&p_W1f,   g_W1f);
    cudaGetSymbolAddress((void**)&p_hfhi,  g_hfhi);
    cudaGetSymbolAddress((void**)&p_hflo,  g_hflo);

    cudaFuncSetAttribute(mm_kernel<0>, cudaFuncAttributeMaxDynamicSharedMemorySize, MM0_SMEM);
    cudaFuncSetAttribute(mm_kernel<1>, cudaFuncAttributeMaxDynamicSharedMemorySize, MM1_SMEM);
    cudaFuncSetAttribute(rnn_kernel,   cudaFuncAttributeMaxDynamicSharedMemorySize, RNN_SMEM);

    // 1. split weights + bias
    prep_w_kernel<<<4096, 256>>>(Wih_f, Wih_b, bih_f, bih_b, Whh_f, Whh_b, W1);
    // 2. split x
    prep_a_kernel<<<32768, 256>>>(x);
    // 3. xw = x @ Wcat^T + bcat   (bf16 3-product)
    mm_kernel<0><<<dim3(8, 256), 256, MM0_SMEM>>>(p_Ahi, p_Alo, p_Whi, p_Wlo,
                                                  p_bcat, nullptr, nullptr, p_xw);
    // 4. sproj = s @ W1[:, :N]^T + b1 (split-K + reduce)
    gemm_small<<<dim3(8, 8), 256>>>(s, W1);
    reduce_sproj<<<256, 256>>>(b1);
    // 5. bidirectional recurrence (tensor cores, split cluster barrier)
    rnn_kernel<<<64, 256, RNN_SMEM>>>(bhh_f, bhh_b);
    // 6. attention MLP + dot with w2 (fp16 2-product, fused epilogue)
    mm_kernel<1><<<dim3(8, 256), 256, MM1_SMEM>>>(
        (const __nv_bfloat16*)p_hfhi, (const __nv_bfloat16*)p_hflo,
        (const __nv_bfloat16*)p_W1f, nullptr,
        nullptr, p_sproj, W2, p_epart);
    // 7. softmax over time
    softmax_kernel<<<64, 512>>>(b2);
    // 8. weighted sum -> output [B, N]
    out_kernel<<<dim3(64, 4), 256>>>(out);
}

// round 13
// speedup vs baseline: 1.0477x; 1.0058x over previous
#include <cuda_runtime.h>
#include <cuda_bf16.h>
#include <cuda_fp16.h>
#include <math.h>
#include <stdint.h>

#define T_DIM 512
#define B_DIM 64
#define N_DIM 1024
#define H_DIM 512
#define M_DIM (T_DIM*B_DIM)   // 32768 rows = (t,b)

// ================= scratch (device globals) =================
__device__ float g_bcat[N_DIM];
__device__ float g_xw[M_DIM*N_DIM];            // input projections [32768][1024]
__device__ __half g_hfhi[M_DIM*N_DIM];         // hidden split hi (fp16)
__device__ __half g_hflo[M_DIM*N_DIM];         // hidden split lo (fp16)
__device__ __nv_bfloat16 g_Ahi[M_DIM*N_DIM];   // x split hi
__device__ __nv_bfloat16 g_Alo[M_DIM*N_DIM];   // x split lo
__device__ __nv_bfloat16 g_Whi[N_DIM*N_DIM];   // [Wih_f;Wih_b] split
__device__ __nv_bfloat16 g_Wlo[N_DIM*N_DIM];
__device__ __half g_W1f[N_DIM*N_DIM];          // W1[:,1024:2048] fp16 (single plane)
__device__ __nv_bfloat16 g_Whhhi[2*H_DIM*H_DIM]; // Whh split [dir][j][k]
__device__ __nv_bfloat16 g_Whhlo[2*H_DIM*H_DIM];
__device__ __nv_bfloat16 g_state_hi[2*2*B_DIM*H_DIM]; // ping-pong [buf][dir][b][k]
__device__ __nv_bfloat16 g_state_lo[2*2*B_DIM*H_DIM];
__device__ float g_sproj[B_DIM*N_DIM];         // s @ W1[:, :N]^T + b1
__device__ float g_spart[8*B_DIM*N_DIM];       // split-K partials for sproj
__device__ float g_epart[8*M_DIM];             // per-ntile partial logits
__device__ float g_attn[T_DIM*B_DIM];          // softmax weights

__device__ __forceinline__ void split_bf16(float a, __nv_bfloat16& hi, __nv_bfloat16& lo) {
    hi = __float2bfloat16(a);
    lo = __float2bfloat16(a - __bfloat162float(hi));
}
__device__ __forceinline__ void split_fp16(float a, __half& hi, __half& lo) {
    hi = __float2half(a);
    lo = __float2half(a - __half2float(hi));
}

// ---------------- mma.sync + cp.async + ldmatrix primitives ----------------
__device__ __forceinline__ void mma16816(float* d, const uint32_t* a, uint32_t b0, uint32_t b1) {
    asm volatile("mma.sync.aligned.m16n8k16.row.col.f32.bf16.bf16.f32 "
        "{%0,%1,%2,%3}, {%4,%5,%6,%7}, {%8,%9}, {%0,%1,%2,%3};"
        : "+f"(d[0]), "+f"(d[1]), "+f"(d[2]), "+f"(d[3])
        : "r"(a[0]), "r"(a[1]), "r"(a[2]), "r"(a[3]), "r"(b0), "r"(b1));
}
__device__ __forceinline__ void mma16816h(float* d, const uint32_t* a, uint32_t b0, uint32_t b1) {
    asm volatile("mma.sync.aligned.m16n8k16.row.col.f32.f16.f16.f32 "
        "{%0,%1,%2,%3}, {%4,%5,%6,%7}, {%8,%9}, {%0,%1,%2,%3};"
        : "+f"(d[0]), "+f"(d[1]), "+f"(d[2]), "+f"(d[3])
        : "r"(a[0]), "r"(a[1]), "r"(a[2]), "r"(a[3]), "r"(b0), "r"(b1));
}
__device__ __forceinline__ uint32_t smem_u32(const void* p) {
    uint32_t a;
    asm("{ .reg .u64 t; cvta.to.shared.u64 t, %1; cvt.u32.u64 %0, t; }" : "=r"(a) : "l"(p));
    return a;
}
#define LDSM_X4(r, addr) \
    asm volatile("ldmatrix.sync.aligned.m8n8.x4.shared.b16 {%0,%1,%2,%3}, [%4];" \
        : "=r"((r)[0]), "=r"((r)[1]), "=r"((r)[2]), "=r"((r)[3]) : "r"(addr))
#define CP_ASYNC16(dst_u32, src) \
    asm volatile("cp.async.cg.shared.global [%0], [%1], 16;" :: "r"(dst_u32), "l"(src))
#define CP_COMMIT() asm volatile("cp.async.commit_group;" ::: "memory")
#define CP_WAIT(n)  asm volatile("cp.async.wait_group %0;" :: "n"(n) : "memory")

// ---------------- prep: weights split + bias ----------------
__global__ void prep_w_kernel(const float* __restrict__ Wih_f, const float* __restrict__ Wih_b,
                              const float* __restrict__ bih_f, const float* __restrict__ bih_b,
                              const float* __restrict__ Whh_f, const float* __restrict__ Whh_b,
                              const float* __restrict__ W1)
{
    int idx = blockIdx.x * 256 + threadIdx.x;     // 0..1M-1
    int j = idx >> 10, k = idx & 1023;
    float wc = (j < 512) ? Wih_f[j*1024 + k] : Wih_b[(j-512)*1024 + k];
    __nv_bfloat16 hi, lo;
    split_bf16(wc, hi, lo);
    g_Whi[idx] = hi; g_Wlo[idx] = lo;
    g_W1f[idx] = __float2half(W1[j*2048 + 1024 + k]);
    if (idx < 2*H_DIM*H_DIM) {
        int d = idx >> 18;
        int off = idx & (H_DIM*H_DIM - 1);
        float wv = (d ? Whh_b : Whh_f)[off];
        split_bf16(wv, hi, lo);
        g_Whhhi[idx] = hi; g_Whhlo[idx] = lo;
    }
    if (idx < N_DIM) g_bcat[idx] = (idx < 512) ? bih_f[idx] : bih_b[idx-512];
}

// ---------------- prep: x split ----------------
__global__ void prep_a_kernel(const float* __restrict__ x)
{
    int i4 = blockIdx.x * 256 + threadIdx.x;
    float4 v = ((const float4*)x)[i4];
    __nv_bfloat16 h0,h1,h2,h3,l0,l1,l2,l3;
    split_bf16(v.x,h0,l0); split_bf16(v.y,h1,l1);
    split_bf16(v.z,h2,l2); split_bf16(v.w,h3,l3);
    int base = i4 * 4;
    *(__nv_bfloat162*)&g_Ahi[base]   = __halves2bfloat162(h0,h1);
    *(__nv_bfloat162*)&g_Ahi[base+2] = __halves2bfloat162(h2,h3);
    *(__nv_bfloat162*)&g_Alo[base]   = __halves2bfloat162(l0,l1);
    *(__nv_bfloat162*)&g_Alo[base+2] = __halves2bfloat162(l2,l3);
}

// ================= mma.sync GEMM =================
// MODE 0: bf16 3-product (Ahi,Alo,Bhi,Blo): C[r][n] = acc + bias[n]
// MODE 1: fp16 2-product (Ahi,Alo,B): v=tanh(acc+sproj); epart[bx][r]=sum v*w2
#define SA 40
#define ARR_B (128*SA*2)
#define MM_STAGES 4
#define MM0_SMEM (MM_STAGES*4*ARR_B)   // 163840
#define MM1_SMEM (MM_STAGES*3*ARR_B)   // 122880
template<int MODE>
__global__ void __launch_bounds__(256) mm_kernel(
    const __nv_bfloat16* __restrict__ Ahi, const __nv_bfloat16* __restrict__ Alo,
    const __nv_bfloat16* __restrict__ Bhi, const __nv_bfloat16* __restrict__ Blo,
    const float* __restrict__ bias,
    const float* __restrict__ sproj, const float* __restrict__ w2,
    float* __restrict__ C)
{
    extern __shared__ char smem[];
    const uint32_t sb = smem_u32(smem);
    constexpr int NARR = (MODE == 0) ? 4 : 3;
    constexpr uint32_t STG = (uint32_t)(NARR * ARR_B);

    const int tid = threadIdx.x;
    const int wid = tid >> 5, lane = tid & 31;
    const int warp_m = wid & 3, warp_n = wid >> 2;
    const int g = lane >> 2, q = lane & 3;
    const int n0 = blockIdx.x * 128;
    const int m0 = blockIdx.y * 128;

    const int l = lane;
    const uint32_t aoffB = (uint32_t)((((l & 7) + ((l >> 3) & 1) * 8) * SA + ((l >> 4) * 8))) * 2u;
    const uint32_t boffB = (uint32_t)(((((l >> 4) * 8) + (l & 7)) * SA + (((l >> 3) & 1) * 8))) * 2u;

    const int row0c = tid >> 2, sc0 = tid & 3;
    const int row1c = (tid + 256) >> 2, sc1 = (tid + 256) & 3;

    auto issue_chunk = [&](int kc) {
        uint32_t sbase = sb + (uint32_t)(kc % MM_STAGES) * STG;
        int col0 = kc * 32 + sc0 * 8;
        int col1 = kc * 32 + sc1 * 8;
        uint32_t so0 = (uint32_t)(row0c * (SA*2) + sc0 * 16);
        uint32_t so1 = (uint32_t)(row1c * (SA*2) + sc1 * 16);
        CP_ASYNC16(sbase + 0*ARR_B + so0, Ahi + (size_t)(m0 + row0c)*1024 + col0);
        CP_ASYNC16(sbase + 0*ARR_B + so1, Ahi + (size_t)(m0 + row1c)*1024 + col1);
        CP_ASYNC16(sbase + 1*ARR_B + so0, Alo + (size_t)(m0 + row0c)*1024 + col0);
        CP_ASYNC16(sbase + 1*ARR_B + so1, Alo + (size_t)(m0 + row1c)*1024 + col1);
        CP_ASYNC16(sbase + 2*ARR_B + so0, Bhi + (size_t)(n0 + row0c)*1024 + col0);
        CP_ASYNC16(sbase + 2*ARR_B + so1, Bhi + (size_t)(n0 + row1c)*1024 + col1);
        if (MODE == 0) {
            CP_ASYNC16(sbase + 3*ARR_B + so0, Blo + (size_t)(n0 + row0c)*1024 + col0);
            CP_ASYNC16(sbase + 3*ARR_B + so1, Blo + (size_t)(n0 + row1c)*1024 + col1);
        }
        CP_COMMIT();
    };

    float acc[2][8][4];
    #pragma unroll
    for (int mt = 0; mt < 2; mt++)
        #pragma unroll
        for (int nt = 0; nt < 8; nt++)
            #pragma unroll
            for (int i = 0; i < 4; i++) acc[mt][nt][i] = 0.f;

    issue_chunk(0);
    issue_chunk(1);
    issue_chunk(2);

    const int NC = 32;
    for (int kc = 0; kc < NC; ++kc) {
        CP_WAIT(2);
        __syncthreads();
        if (kc + 3 < NC) issue_chunk(kc + 3);
        else CP_COMMIT();                    // keep group count constant (hard guarantee)

        const uint32_t stage = sb + (uint32_t)(kc % MM_STAGES) * STG;
        const uint32_t aHi = stage + (uint32_t)(warp_m*32*SA*2) + aoffB;
        const uint32_t aLo = aHi + ARR_B;
        const uint32_t bHi = stage + 2*ARR_B + (uint32_t)(warp_n*64*SA*2) + boffB;

        #pragma unroll
        for (int ks = 0; ks < 2; ks++) {
            const uint32_t ko = (uint32_t)(ks * 32);
            uint32_t ah[2][4], al[2][4];
            #pragma unroll
            for (int mt = 0; mt < 2; mt++) {
                LDSM_X4(ah[mt], aHi + (uint32_t)(mt*16*SA*2) + ko);
                LDSM_X4(al[mt], aLo + (uint32_t)(mt*16*SA*2) + ko);
            }
            #pragma unroll
            for (int ntp = 0; ntp < 4; ntp++) {
                uint32_t bh[4];
                LDSM_X4(bh, bHi + (uint32_t)(ntp*16*SA*2) + ko);
                if (MODE == 0) {
                    uint32_t bl[4];
                    LDSM_X4(bl, bHi + ARR_B + (uint32_t)(ntp*16*SA*2) + ko);
                    #pragma unroll
                    for (int half = 0; half < 2; half++) {
                        const int nt = ntp*2 + half;
                        #pragma unroll
                        for (int mt = 0; mt < 2; mt++) {
                            mma16816(acc[mt][nt], ah[mt], bh[half*2], bh[half*2+1]);
                            mma16816(acc[mt][nt], ah[mt], bl[half*2], bl[half*2+1]);
                            mma16816(acc[mt][nt], al[mt], bh[half*2], bh[half*2+1]);
                        }
                    }
                } else {
                    #pragma unroll
                    for (int half = 0; half < 2; half++) {
                        const int nt = ntp*2 + half;
                        #pragma unroll
                        for (int mt = 0; mt < 2; mt++) {
                            mma16816h(acc[mt][nt], ah[mt], bh[half*2], bh[half*2+1]);
                            mma16816h(acc[mt][nt], al[mt], bh[half*2], bh[half*2+1]);
                        }
                    }
                }
            }
        }
    }
    __syncthreads();

    if (MODE == 0) {
        #pragma unroll
        for (int mt = 0; mt < 2; mt++) {
            const int r = m0 + warp_m*32 + mt*16 + g;
            #pragma unroll
            for (int nt = 0; nt < 8; nt++) {
                const int c = n0 + warp_n*64 + nt*8 + q*2;
                float b0 = bias[c], b1 = bias[c+1];
                float2 v0 = make_float2(acc[mt][nt][0] + b0, acc[mt][nt][1] + b1);
                float2 v1 = make_float2(acc[mt][nt][2] + b0, acc[mt][nt][3] + b1);
                *(float2*)&C[(size_t)r*1024 + c]       = v0;
                *(float2*)&C[(size_t)(r+8)*1024 + c]   = v1;
            }
        }
    } else {
        float* red = (float*)smem;
        #pragma unroll
        for (int mt = 0; mt < 2; mt++) {
            const int rloc0 = warp_m*32 + mt*16 + g;
            const float* sp0 = &sproj[((m0 + rloc0)     & 63) * N_DIM];
            const float* sp1 = &sproj[((m0 + rloc0 + 8) & 63) * N_DIM];
            float s0 = 0.f, s1 = 0.f;
            #pragma unroll
            for (int nt = 0; nt < 8; nt++) {
                const int c = n0 + warp_n*64 + nt*8 + q*2;
                float w20 = w2[c], w21 = w2[c+1];
                s0 += tanhf(acc[mt][nt][0] + sp0[c])   * w20
                    + tanhf(acc[mt][nt][1] + sp0[c+1]) * w21;
                s1 += tanhf(acc[mt][nt][2] + sp1[c])   * w20
                    + tanhf(acc[mt][nt][3] + sp1[c+1]) * w21;
            }
            s0 += __shfl_xor_sync(0xffffffffu, s0, 1);
            s0 += __shfl_xor_sync(0xffffffffu, s0, 2);
            s1 += __shfl_xor_sync(0xffffffffu, s1, 1);
            s1 += __shfl_xor_sync(0xffffffffu, s1, 2);
            if (q == 0) {
                red[rloc0*2 + warp_n]     = s0;
                red[(rloc0+8)*2 + warp_n] = s1;
            }
        }
        __syncthreads();
        if (tid < 128)
            C[blockIdx.x * M_DIM + m0 + tid] = red[tid*2] + red[tid*2 + 1];
    }
}

// ---------------- sproj: split-K fp32 SIMT GEMM + reduce ----------------
__global__ void __launch_bounds__(256) gemm_small(
    const float* __restrict__ A, const float* __restrict__ Bw)
{
    __shared__ float As[16][128];
    __shared__ float Bs[16][128];

    const int tid  = threadIdx.x;
    const int n0   = blockIdx.x * 128;
    const int kb   = blockIdx.y * 128;
    const int lrow = tid >> 2;
    const int lcol = (tid & 3) << 2;
    const int rm   = (tid >> 4) << 3;
    const int rn   = (tid & 15) << 3;

    float4 pa0, pb0, pb1;
    auto loadg = [&](int kt) {
        float4 z; z.x = z.y = z.z = z.w = 0.f;
        pa0 = (lrow < 64) ? *(const float4*)&A[lrow*1024 + kb + kt + lcol] : z;
        pb0 = *(const float4*)&Bw[(n0 + lrow)      * 2048 + kb + kt + lcol];
        pb1 = *(const float4*)&Bw[(n0 + lrow + 64) * 2048 + kb + kt + lcol];
    };
    auto stores = [&]() {
        if (lrow < 64) {
            As[lcol+0][lrow] = pa0.x; As[lcol+1][lrow] = pa0.y;
            As[lcol+2][lrow] = pa0.z; As[lcol+3][lrow] = pa0.w;
        } else {
            int lr = lrow - 64;
            As[lcol+0][lr+64] = 0.f; As[lcol+1][lr+64] = 0.f;
            As[lcol+2][lr+64] = 0.f; As[lcol+3][lr+64] = 0.f;
        }
        Bs[lcol+0][lrow]    = pb0.x; Bs[lcol+1][lrow]    = pb0.y;
        Bs[lcol+2][lrow]    = pb0.z; Bs[lcol+3][lrow]    = pb0.w;
        Bs[lcol+0][lrow+64] = pb1.x; Bs[lcol+1][lrow+64] = pb1.y;
        Bs[lcol+2][lrow+64] = pb1.z; Bs[lcol+3][lrow+64] = pb1.w;
    };

    float acc[8][8];
    #pragma unroll
    for (int i = 0; i < 8; i++)
        #pragma unroll
        for (int j = 0; j < 8; j++) acc[i][j] = 0.f;

    loadg(0); stores(); __syncthreads();
    const int NIT = 8;
    for (int it = 0; it < NIT; ++it) {
        if (it + 1 < NIT) loadg((it + 1) * 16);
        #pragma unroll
        for (int k = 0; k < 16; k++) {
            float4 a0 = *(const float4*)&As[k][rm];
            float4 a1 = *(const float4*)&As[k][rm + 4];
            float4 b0 = *(const float4*)&Bs[k][rn];
            float4 b1 = *(const float4*)&Bs[k][rn + 4];
            float av[8] = {a0.x,a0.y,a0.z,a0.w,a1.x,a1.y,a1.z,a1.w};
            float bv[8] = {b0.x,b0.y,b0.z,b0.w,b1.x,b1.y,b1.z,b1.w};
            #pragma unroll
            for (int i = 0; i < 8; i++)
                #pragma unroll
                for (int j = 0; j < 8; j++)
                    acc[i][j] += av[i] * bv[j];
        }
        if (it + 1 < NIT) { __syncthreads(); stores(); __syncthreads(); }
    }
    float* Cp = &g_spart[blockIdx.y * (B_DIM*N_DIM)];
    #pragma unroll
    for (int i = 0; i < 8; i++) {
        int rr = rm + i;
        if (rr < 64) {
            #pragma unroll
            for (int j = 0; j < 8; j++)
                Cp[rr*1024 + n0 + rn + j] = acc[i][j];
        }
    }
}

__global__ void __launch_bounds__(256) reduce_sproj(const float* __restrict__ b1)
{
    int idx = blockIdx.x * 256 + threadIdx.x;
    float s = b1[idx & 1023];
    #pragma unroll
    for (int k = 0; k < 8; k++) s += g_spart[k * (B_DIM*N_DIM) + idx];
    g_sproj[idx] = s;
}

// ---------------- bidirectional recurrence: tensor-core, split cluster barrier ----------------
#define RSA 520
#define RNN_HS_B (16*RSA*2)
#define RED_S 68
#define RNN_RED_OFF (2*RNN_HS_B)
#define RNN_SMEM (RNN_RED_OFF + 8*16*RED_S*4)

__global__ void __launch_bounds__(256) __cluster_dims__(8, 1, 1)
rnn_kernel(const float* __restrict__ bhh_f, const float* __restrict__ bhh_b)
{
    extern __shared__ char smem[];
    float* red = (float*)(smem + RNN_RED_OFF);
    const uint32_t sb = smem_u32(smem);

    const int tid = threadIdx.x;
    const int wid = tid >> 5, lane = tid & 31;
    const int g = lane >> 2, q = lane & 3;
    const int bx = blockIdx.x;
    const int cid = bx >> 3;
    const int jtile = bx & 7;
    const int dir = cid >> 2;
    const int btile = cid & 3;

    const float* bhh = dir ? bhh_b : bhh_f;
    const __nv_bfloat16* Whi = g_Whhhi + dir * (H_DIM*H_DIM);
    const __nv_bfloat16* Wlo = g_Whhlo + dir * (H_DIM*H_DIM);

    uint32_t bh[8][4][2], bl[8][4][2];
    #pragma unroll
    for (int nt = 0; nt < 8; nt++) {
        int jg = jtile*64 + nt*8 + g;
        #pragma unroll
        for (int kt = 0; kt < 4; kt++) {
            int k = wid*64 + kt*16 + q*2;
            bh[nt][kt][0] = *(const uint32_t*)&Whi[jg*512 + k];
            bh[nt][kt][1] = *(const uint32_t*)&Whi[jg*512 + k + 8];
            bl[nt][kt][0] = *(const uint32_t*)&Wlo[jg*512 + k];
            bl[nt][kt][1] = *(const uint32_t*)&Wlo[jg*512 + k + 8];
        }
    }

    const int l = lane;
    const uint32_t aoffR = (uint32_t)((((l & 7) + ((l >> 3) & 1) * 8) * RSA + ((l >> 4) * 8))) * 2u;

    for (int o = tid; o < 16*64; o += 256) {
        int b = btile*16 + (o >> 6);
        int j = jtile*64 + (o & 63);
        int idx = (dir*64 + b)*512 + j;
        g_state_hi[idx] = __float2bfloat16(0.f);
        g_state_lo[idx] = __float2bfloat16(0.f);
    }
    asm volatile("barrier.cluster.arrive.release.aligned;\n\t"
                 "barrier.cluster.wait.acquire.aligned;" ::: "memory");

    const int fb  = tid >> 4;
    const int fj4 = (tid & 15) * 4;
    const int bg  = btile*16 + fb;
    const int jg0 = jtile*64 + fj4;
    const float4 bj = *(const float4*)&bhh[jg0];

    for (int t = 0; t < T_DIM; ++t) {
        const int rbuf = t & 1, wbuf = rbuf ^ 1;
        const int tt  = dir ? (T_DIM - 1 - t) : t;
        const size_t hidx = (size_t)(tt*64 + bg)*1024 + dir*512 + jg0;
        float4 xwv = *(const float4*)&g_xw[hidx];

        {
            const __nv_bfloat16* shi = g_state_hi + ((rbuf*2 + dir)*64 + btile*16)*512;
            const __nv_bfloat16* slo = g_state_lo + ((rbuf*2 + dir)*64 + btile*16)*512;
            #pragma unroll
            for (int i = 0; i < 8; i++) {
                int c = tid + i*256;
                int plane = c >> 10, rr = (c >> 6) & 15, seg = c & 63;
                const __nv_bfloat16* sp = (plane ? slo : shi) + rr*512 + seg*8;
                uint32_t dst = sb + (plane ? RNN_HS_B : 0) + (uint32_t)(rr*1040 + seg*16);
                CP_ASYNC16(dst, sp);
            }
            CP_COMMIT();
            CP_WAIT(0);
        }
        __syncthreads();

        float acc[8][4];
        #pragma unroll
        for (int nt = 0; nt < 8; nt++)
            #pragma unroll
            for (int i = 0; i < 4; i++) acc[nt][i] = 0.f;

        #pragma unroll
        for (int kt = 0; kt < 4; kt++) {
            const uint32_t kByte = (uint32_t)((wid*64 + kt*16) * 2);
            uint32_t ah[4], al[4];
            LDSM_X4(ah, sb + kByte + aoffR);
            LDSM_X4(al, sb + RNN_HS_B + kByte + aoffR);
            #pragma unroll
            for (int nt = 0; nt < 8; nt++) {
                mma16816(acc[nt], ah, bh[nt][kt][0], bh[nt][kt][1]);
                mma16816(acc[nt], ah, bl[nt][kt][0], bl[nt][kt][1]);
                mma16816(acc[nt], al, bh[nt][kt][0], bh[nt][kt][1]);
            }
        }

        #pragma unroll
        for (int nt = 0; nt < 8; nt++) {
            *(float2*)&red[(wid*16 + g)*RED_S + nt*8 + q*2]     = make_float2(acc[nt][0], acc[nt][1]);
            *(float2*)&red[(wid*16 + g + 8)*RED_S + nt*8 + q*2] = make_float2(acc[nt][2], acc[nt][3]);
        }
        __syncthreads();

        {
            float4 s = make_float4(0.f, 0.f, 0.f, 0.f);
            #pragma unroll
            for (int w8 = 0; w8 < 8; w8++) {
                float4 p = *(const float4*)&red[(w8*16 + fb)*RED_S + fj4];
                s.x += p.x; s.y += p.y; s.z += p.z; s.w += p.w;
            }
            float v0 = tanhf(s.x + xwv.x + bj.x);
            float v1 = tanhf(s.y + xwv.y + bj.y);
            float v2 = tanhf(s.z + xwv.z + bj.z);
            float v3 = tanhf(s.w + xwv.w + bj.w);

            __nv_bfloat16 h0,h1,h2,h3,l0,l1,l2,l3;
            split_bf16(v0,h0,l0); split_bf16(v1,h1,l1);
            split_bf16(v2,h2,l2); split_bf16(v3,h3,l3);

            const size_t sidx = ((size_t)(wbuf*2 + dir)*64 + bg)*512 + jg0;
            *(__nv_bfloat162*)&g_state_hi[sidx]   = __halves2bfloat162(h0,h1);
            *(__nv_bfloat162*)&g_state_hi[sidx+2] = __halves2bfloat162(h2,h3);
            *(__nv_bfloat162*)&g_state_lo[sidx]   = __halves2bfloat162(l0,l1);
            *(__nv_bfloat162*)&g_state_lo[sidx+2] = __halves2bfloat162(l2,l3);
            __syncthreads();   // all CTA threads' state stores done before arrive
            asm volatile("barrier.cluster.arrive.release.aligned;" ::: "memory");

            // history stores overlap the barrier wait (fp16 planes only; fp32 h
            // plane removed — out_kernel reconstructs h = hi + lo)
            __half f0,f1,f2,f3,e0,e1,e2,e3;
            split_fp16(v0,f0,e0); split_fp16(v1,f1,e1);
            split_fp16(v2,f2,e2); split_fp16(v3,f3,e3);
            *(__half2*)&g_hfhi[hidx]   = __halves2half2(f0,f1);
            *(__half2*)&g_hfhi[hidx+2] = __halves2half2(f2,f3);
            *(__half2*)&g_hflo[hidx]   = __halves2half2(e0,e1);
            *(__half2*)&g_hflo[hidx+2] = __halves2half2(e2,e3);

            asm volatile("barrier.cluster.wait.acquire.aligned;" ::: "memory");
        }
    }
}

// ---------------- softmax over time ----------------
__global__ void __launch_bounds__(512) softmax_kernel(const float* __restrict__ b2)
{
    const int b = blockIdx.x;
    const int t = threadIdx.x;
    float s = 0.f;
    #pragma unroll
    for (int p = 0; p < 8; p++) s += g_epart[p * M_DIM + t * 64 + b];
    float e = tanhf(s + b2[0]);

    __shared__ float sm[512];
    sm[t] = e; __syncthreads();
    for (int st = 256; st > 0; st >>= 1) {
        if (t < st) sm[t] = fmaxf(sm[t], sm[t + st]);
        __syncthreads();
    }
    float mx = sm[0]; __syncthreads();
    float ex = expf(e - mx);
    sm[t] = ex; __syncthreads();
    for (int st = 256; st > 0; st >>= 1) {
        if (t < st) sm[t] += sm[t + st];
        __syncthreads();
    }
    g_attn[t * 64 + b] = ex / sm[0];
}

// ---------------- weighted sum over time (h reconstructed from fp16 planes) ----------------
__global__ void __launch_bounds__(256) out_kernel(float* __restrict__ out)
{
    const int b  = blockIdx.x;
    const int n  = blockIdx.y * 256 + threadIdx.x;
    __shared__ float a_s[512];
    for (int t = threadIdx.x; t < 512; t += 256) a_s[t] = g_attn[t * 64 + b];
    __syncthreads();
    float acc = 0.f;
    const __half* hpi = &g_hfhi[(size_t)b * 1024 + n];
    const __half* hpl = &g_hflo[(size_t)b * 1024 + n];
    #pragma unroll 8
    for (int t = 0; t < 512; t++) {
        float hv = __half2float(hpi[(size_t)t * 65536]) + __half2float(hpl[(size_t)t * 65536]);
        acc += a_s[t] * hv;
    }
    out[b * 1024 + n] = acc;
}

// ---------------- launch ----------------
extern "C" void kernel_launch(void* const* d_in, const int* in_sizes, int n_in,
                              void* d_out, int out_size)
{
    const float* s     = (const float*)d_in[0];
    const float* x     = (const float*)d_in[1];
    const float* Wih_f = (const float*)d_in[2];
    const float* Whh_f = (const float*)d_in[3];
    const float* bih_f = (const float*)d_in[4];
    const float* bhh_f = (const float*)d_in[5];
    const float* Wih_b = (const float*)d_in[6];
    const float* Whh_b = (const float*)d_in[7];
    const float* bih_b = (const float*)d_in[8];
    const float* bhh_b = (const float*)d_in[9];
    const float* W1    = (const float*)d_in[10];
    const float* b1    = (const float*)d_in[11];
    const float* W2    = (const float*)d_in[12];
    const float* b2    = (const float*)d_in[13];
    float* out = (float*)d_out;

    float *p_bcat, *p_xw, *p_sproj, *p_epart;
    __nv_bfloat16 *p_Ahi, *p_Alo, *p_Whi, *p_Wlo;
    __half *p_W1f, *p_hfhi, *p_hflo;
    cudaGetSymbolAddress((void**)&p_bcat,  g_bcat);
    cudaGetSymbolAddress((void**)&p_xw,    g_xw);
    cudaGetSymbolAddress((void**)&p_sproj, g_sproj);
    cudaGetSymbolAddress((void**)&p_epart, g_epart);
    cudaGetSymbolAddress((void**)&p_Ahi,   g_Ahi);
    cudaGetSymbolAddress((void**)&p_Alo,   g_Alo);
    cudaGetSymbolAddress((void**)&p_Whi,   g_Whi);
    cudaGetSymbolAddress((void**)&p_Wlo,   g_Wlo);
    cudaGetSymbolAddress((void**)&p_W1f,   g_W1f);
    cudaGetSymbolAddress((void**)&p_hfhi,  g_hfhi);
    cudaGetSymbolAddress((void**)&p_hflo,  g_hflo);

    cudaFuncSetAttribute(mm_kernel<0>, cudaFuncAttributeMaxDynamicSharedMemorySize, MM0_SMEM);
    cudaFuncSetAttribute(mm_kernel<1>, cudaFuncAttributeMaxDynamicSharedMemorySize, MM1_SMEM);
    cudaFuncSetAttribute(rnn_kernel,   cudaFuncAttributeMaxDynamicSharedMemorySize, RNN_SMEM);

    // 1. split weights + bias
    prep_w_kernel<<<4096, 256>>>(Wih_f, Wih_b, bih_f, bih_b, Whh_f, Whh_b, W1);
    // 2. split x
    prep_a_kernel<<<32768, 256>>>(x);
    // 3. xw = x @ Wcat^T + bcat   (bf16 3-product)
    mm_kernel<0><<<dim3(8, 256), 256, MM0_SMEM>>>(p_Ahi, p_Alo, p_Whi, p_Wlo,
                                                  p_bcat, nullptr, nullptr, p_xw);
    // 4. bidirectional recurrence — LAUNCH SLOT 4 (ncu capture target)
    rnn_kernel<<<64, 256, RNN_SMEM>>>(bhh_f, bhh_b);
    // 5. sproj = s @ W1[:, :N]^T + b1 (split-K + reduce; only needed before mm1)
    gemm_small<<<dim3(8, 8), 256>>>(s, W1);
    reduce_sproj<<<256, 256>>>(b1);
    // 6. attention MLP + dot with w2 (fp16 2-product, fused epilogue)
    mm_kernel<1><<<dim3(8, 256), 256, MM1_SMEM>>>(
        (const __nv_bfloat16*)p_hfhi, (const __nv_bfloat16*)p_hflo,
        (const __nv_bfloat16*)p_W1f, nullptr,
        nullptr, p_sproj, W2, p_epart);
    // 7. softmax over time
    softmax_kernel<<<64, 512>>>(b2);
    // 8. weighted sum -> output [B, N]
    out_kernel<<<dim3(64, 4), 256>>>(out);
}